// round 8
// baseline (speedup 1.0000x reference)
#include <cuda_runtime.h>

// ChamferDistance_755914244601: B=4, N=M=8192, 3D points.
// Fused single pass. Packed f32x2 FFMA2/FADD2 distance chain producing full
// distances directly (s1 folded into the chain seed); row mins via
// REDUX.MIN.U32 + global atomicMin, col mins in registers. Double-buffered
// row tiles -> one barrier per chunk.

#define BB 4
#define NN 8192
#define MM 8192
#define BC 256          // cols per block
#define KC 8            // cols per lane
#define NCP (KC / 2)    // colpairs per lane
#define TPB 256
#define NWARP 8
#define CH 128          // rows per chunk
#define RPW (CH / NWARP)
#define ROWSPLIT 16
#define NROWS (NN / ROWSPLIT)   // 512
#define NCHUNK (NROWS / CH)     // 4
#define NCB (MM / BC)   // 32 col blocks

typedef unsigned long long ull;

static __device__ __forceinline__ ull pk2(float lo, float hi) {
    ull r; asm("mov.b64 %0, {%1, %2};" : "=l"(r) : "f"(lo), "f"(hi)); return r;
}
static __device__ __forceinline__ void upk2(ull v, float& lo, float& hi) {
    asm("mov.b64 {%0, %1}, %2;" : "=f"(lo), "=f"(hi) : "l"(v));
}
static __device__ __forceinline__ ull ffma2(ull a, ull b, ull c) {
    ull d; asm("fma.rn.f32x2 %0, %1, %2, %3;" : "=l"(d) : "l"(a), "l"(b), "l"(c)); return d;
}
static __device__ __forceinline__ ull fadd2(ull a, ull b) {
    ull d; asm("add.rn.f32x2 %0, %1, %2;" : "=l"(d) : "l"(a), "l"(b)); return d;
}

// Seed d_out (B*N + B*M floats) with FLT_MAX bit pattern.
__global__ void init_kernel(unsigned int* __restrict__ out)
{
    const int i = blockIdx.x * blockDim.x + threadIdx.x;
    if (i < BB * NN + BB * MM) out[i] = 0x7F7FFFFFu;   // FLT_MAX
}

__global__ void __launch_bounds__(TPB, 3)
chamfer_fused(const float* __restrict__ x1, const float* __restrict__ x2,
              unsigned int* __restrict__ out)
{
    // Row buffers (double-buffered) overlaid with the epilogue col-reduce
    // scratch: rows are dead by the time colred is written (barrier between).
    __shared__ union SmemU {
        struct { ulonglong2 RA[2][CH]; ulonglong2 RB[2][CH]; } rows;  // 8KB
        float colred[NWARP * BC];                                     // 8KB
    } shx;
    __shared__ float4 colsm[BC];      // (-2x,-2y,-2z,s2) per col

    const int tid  = threadIdx.x;
    const int lane = tid & 31;
    const int w    = tid >> 5;
    const int b     = blockIdx.z;
    const int split = blockIdx.y;
    const int colbase  = blockIdx.x * BC;
    const int rowbase0 = split * NROWS;

    // ---- prologue: load + preprocess the 256-col tile ----
    if (tid < BC) {
        const float* p = x2 + ((size_t)b * MM + colbase + tid) * 3;
        float x = p[0], y = p[1], z = p[2];
        colsm[tid] = make_float4(-2.0f * x, -2.0f * y, -2.0f * z,
                                 x * x + y * y + z * z);
    }

    // stage chunk 0 into buffer 0
    if (tid < CH) {
        const float* p = x1 + ((size_t)b * NN + rowbase0 + tid) * 3;
        float x = p[0], y = p[1], z = p[2];
        float s = x * x + y * y + z * z;
        shx.rows.RA[0][tid] = make_ulonglong2(pk2(x, x), pk2(y, y));
        shx.rows.RB[0][tid] = make_ulonglong2(pk2(z, z), pk2(s, s));
    }
    __syncthreads();

    // Each lane caches its 4 colpairs in registers (every warp duplicates).
    ull cxx[NCP], cyy[NCP], czz[NCP], cww[NCP];
#pragma unroll
    for (int cp = 0; cp < NCP; cp++) {
        float4 a = colsm[lane * KC + 2 * cp];
        float4 c = colsm[lane * KC + 2 * cp + 1];
        cxx[cp] = pk2(a.x, c.x);
        cyy[cp] = pk2(a.y, c.y);
        czz[cp] = pk2(a.z, c.z);
        cww[cp] = pk2(a.w, c.w);
    }

    float colacc[KC];
#pragma unroll
    for (int j = 0; j < KC; j++) colacc[j] = 3.4e38f;

    // prefetch chunk 1 rows into registers
    float prx = 0.f, pry = 0.f, prz = 0.f;
    if (tid < CH && NCHUNK > 1) {
        const float* p = x1 + ((size_t)b * NN + rowbase0 + CH + tid) * 3;
        prx = p[0]; pry = p[1]; prz = p[2];
    }

    // ---- main loop: one barrier per chunk ----
    for (int ch = 0; ch < NCHUNK; ch++) {
        const int buf = ch & 1;
        const int rowbase = rowbase0 + ch * CH;

        // warps 0-3: stage chunk ch+1 into the other buffer (overlaps compute)
        if (tid < CH && ch + 1 < NCHUNK) {
            float s = prx * prx + pry * pry + prz * prz;
            shx.rows.RA[buf ^ 1][tid] = make_ulonglong2(pk2(prx, prx), pk2(pry, pry));
            shx.rows.RB[buf ^ 1][tid] = make_ulonglong2(pk2(prz, prz), pk2(s, s));
            if (ch + 2 < NCHUNK) {
                const float* p = x1 + ((size_t)b * NN + rowbase + 2 * CH + tid) * 3;
                prx = p[0]; pry = p[1]; prz = p[2];
            }
        }

        // warp w handles rows [w*16, w*16+16) of this chunk
#pragma unroll 4
        for (int rr = 0; rr < RPW; rr++) {
            const int r = w * RPW + rr;
            const ulonglong2 ra = shx.rows.RA[buf][r];   // LDS.128 broadcast
            const ulonglong2 rb = shx.rows.RB[buf][r];
            float rmin = 3.4e38f;
#pragma unroll
            for (int cp = 0; cp < NCP; cp++) {
                // c = (s1+s2) - 2*dot = full squared distance, both halves
                ull seed = fadd2(cww[cp], rb.y);
                ull c = ffma2(cxx[cp], ra.x,
                        ffma2(cyy[cp], ra.y,
                        ffma2(czz[cp], rb.x, seed)));
                float cl, chh; upk2(c, cl, chh);
                colacc[2 * cp]     = fminf(colacc[2 * cp], cl);
                colacc[2 * cp + 1] = fminf(colacc[2 * cp + 1], chh);
                rmin = fminf(rmin, fminf(cl, chh));
            }
            // warp-wide row min: bits of non-negative floats are u32-monotone
            unsigned int um = __reduce_min_sync(0xFFFFFFFFu, __float_as_uint(rmin));
            if (lane == 0)
                atomicMin(&out[(size_t)b * NN + rowbase + r], um);
        }
        __syncthreads();
    }

    // ---- epilogue: reduce colacc across the 8 warps ----
#pragma unroll
    for (int j = 0; j < KC; j++)
        shx.colred[w * BC + lane * KC + j] = colacc[j];
    __syncthreads();
    {
        float m = shx.colred[tid];
#pragma unroll
        for (int ww = 1; ww < NWARP; ww++)
            m = fminf(m, shx.colred[ww * BC + tid]);
        atomicMin(&out[(size_t)(BB * NN) + (size_t)b * MM + colbase + tid],
                  __float_as_uint(m));
    }
}

extern "C" void kernel_launch(void* const* d_in, const int* in_sizes, int n_in,
                              void* d_out, int out_size)
{
    const float* xyz1 = (const float*)d_in[0];   // [B, N, 3]
    const float* xyz2 = (const float*)d_in[1];   // [B, M, 3]
    unsigned int* out = (unsigned int*)d_out;

    const int total = BB * NN + BB * MM;
    init_kernel<<<(total + TPB - 1) / TPB, TPB>>>(out);

    dim3 grid(NCB, ROWSPLIT, BB);   // (32, 16, 4) = 2048 blocks
    chamfer_fused<<<grid, TPB>>>(xyz1, xyz2, out);
}

// round 9
// speedup vs baseline: 1.0711x; 1.0711x over previous
#include <cuda_runtime.h>

// ChamferDistance_755914244601: B=4, N=M=8192, 3D points.
// Fused single pass; packed f32x2 FFMA2/FADD2 chain produces full distances
// (s1 folded into seed). Col mins in registers; row mins via STS cand +
// deferred chunk reduce + uint atomicMin into d_out. KC=4 / 64-reg build
// for 4 blocks/SM occupancy; double-buffered row tiles (2 barriers/chunk).

#define BB 4
#define NN 8192
#define MM 8192
#define BC 128          // cols per block
#define KC 4            // cols per lane
#define NCP (KC / 2)    // colpairs per lane (2)
#define TPB 256
#define NWARP 8
#define CH 128          // rows per chunk
#define RPW (CH / NWARP)
#define ROWSPLIT 16
#define NROWS (NN / ROWSPLIT)   // 512
#define NCHUNK (NROWS / CH)     // 4
#define NCB (MM / BC)   // 64 col blocks

typedef unsigned long long ull;

static __device__ __forceinline__ ull pk2(float lo, float hi) {
    ull r; asm("mov.b64 %0, {%1, %2};" : "=l"(r) : "f"(lo), "f"(hi)); return r;
}
static __device__ __forceinline__ void upk2(ull v, float& lo, float& hi) {
    asm("mov.b64 {%0, %1}, %2;" : "=f"(lo), "=f"(hi) : "l"(v));
}
static __device__ __forceinline__ ull ffma2(ull a, ull b, ull c) {
    ull d; asm("fma.rn.f32x2 %0, %1, %2, %3;" : "=l"(d) : "l"(a), "l"(b), "l"(c)); return d;
}
static __device__ __forceinline__ ull fadd2(ull a, ull b) {
    ull d; asm("add.rn.f32x2 %0, %1, %2;" : "=l"(d) : "l"(a), "l"(b)); return d;
}

// Seed d_out (B*N + B*M floats) with FLT_MAX bit pattern.
__global__ void init_kernel(unsigned int* __restrict__ out)
{
    const int i = blockIdx.x * blockDim.x + threadIdx.x;
    if (i < BB * NN + BB * MM) out[i] = 0x7F7FFFFFu;   // FLT_MAX
}

__global__ void __launch_bounds__(TPB, 4)
chamfer_fused(const float* __restrict__ x1, const float* __restrict__ x2,
              unsigned int* __restrict__ out)
{
    __shared__ ulonglong2 RA[2][CH];   // (x,x),(y,y) per row, double-buffered
    __shared__ ulonglong2 RB[2][CH];   // (z,z),(s1,s1) per row
    __shared__ float4 colsm[BC];       // (-2x,-2y,-2z,s2) per col
    __shared__ union {
        float cand[CH][33];            // row-min candidates (padded stride)
        float colred[NWARP * BC];      // epilogue col-reduce scratch
    } u;

    const int tid  = threadIdx.x;
    const int lane = tid & 31;
    const int w    = tid >> 5;
    const int b     = blockIdx.z;
    const int split = blockIdx.y;
    const int colbase  = blockIdx.x * BC;
    const int rowbase0 = split * NROWS;

    // ---- prologue ----
    if (tid < BC) {
        const float* p = x2 + ((size_t)b * MM + colbase + tid) * 3;
        float x = p[0], y = p[1], z = p[2];
        colsm[tid] = make_float4(-2.0f * x, -2.0f * y, -2.0f * z,
                                 x * x + y * y + z * z);
    }
    if (tid < CH) {   // stage chunk 0 into buffer 0
        const float* p = x1 + ((size_t)b * NN + rowbase0 + tid) * 3;
        float x = p[0], y = p[1], z = p[2];
        float s = x * x + y * y + z * z;
        RA[0][tid] = make_ulonglong2(pk2(x, x), pk2(y, y));
        RB[0][tid] = make_ulonglong2(pk2(z, z), pk2(s, s));
    }
    __syncthreads();

    // Lane's colpair cache (2 colpairs = 4 cols): 16 registers.
    ull cxx[NCP], cyy[NCP], czz[NCP], cww[NCP];
#pragma unroll
    for (int cp = 0; cp < NCP; cp++) {
        float4 a = colsm[lane * KC + 2 * cp];
        float4 c = colsm[lane * KC + 2 * cp + 1];
        cxx[cp] = pk2(a.x, c.x);
        cyy[cp] = pk2(a.y, c.y);
        czz[cp] = pk2(a.z, c.z);
        cww[cp] = pk2(a.w, c.w);
    }

    float colacc[KC];
#pragma unroll
    for (int j = 0; j < KC; j++) colacc[j] = 3.4e38f;

    // prefetch chunk 1 rows into registers
    float prx = 0.f, pry = 0.f, prz = 0.f;
    if (tid < CH && NCHUNK > 1) {
        const float* p = x1 + ((size_t)b * NN + rowbase0 + CH + tid) * 3;
        prx = p[0]; pry = p[1]; prz = p[2];
    }

    // ---- main loop ----
    for (int ch = 0; ch < NCHUNK; ch++) {
        const int buf = ch & 1;
        const int rowbase = rowbase0 + ch * CH;

        // stage chunk ch+1 into the other buffer (overlaps compute below)
        if (tid < CH && ch + 1 < NCHUNK) {
            float s = prx * prx + pry * pry + prz * prz;
            RA[buf ^ 1][tid] = make_ulonglong2(pk2(prx, prx), pk2(pry, pry));
            RB[buf ^ 1][tid] = make_ulonglong2(pk2(prz, prz), pk2(s, s));
            if (ch + 2 < NCHUNK) {
                const float* p = x1 + ((size_t)b * NN + rowbase + 2 * CH + tid) * 3;
                prx = p[0]; pry = p[1]; prz = p[2];
            }
        }

        // warp w handles rows [w*16, w*16+16) of this chunk
#pragma unroll 4
        for (int rr = 0; rr < RPW; rr++) {
            const int r = w * RPW + rr;
            const ulonglong2 ra = RA[buf][r];   // LDS.128 broadcast
            const ulonglong2 rb = RB[buf][r];
            float rmin = 3.4e38f;
#pragma unroll
            for (int cp = 0; cp < NCP; cp++) {
                // c = (s1+s2) - 2*dot  -> full squared distance, both halves
                ull seed = fadd2(cww[cp], rb.y);   // off the critical path
                ull c = ffma2(cxx[cp], ra.x,
                        ffma2(cyy[cp], ra.y,
                        ffma2(czz[cp], rb.x, seed)));
                float cl, chh; upk2(c, cl, chh);
                colacc[2 * cp]     = fminf(colacc[2 * cp], cl);
                colacc[2 * cp + 1] = fminf(colacc[2 * cp + 1], chh);
                rmin = fminf(rmin, fminf(cl, chh));
            }
            u.cand[r][lane] = rmin;   // full distance candidate
        }
        __syncthreads();

        // chunk row-reduce: 2 threads per row, conflict-free (stride-33 pad)
        {
            const int r = tid >> 1;
            const int h = tid & 1;
            float m = u.cand[r][h * 16 + 0];
#pragma unroll
            for (int i = 1; i < 16; i++)
                m = fminf(m, u.cand[r][h * 16 + i]);
            m = fminf(m, __shfl_xor_sync(0xFFFFFFFFu, m, 1));
            if (h == 0)
                atomicMin(&out[(size_t)b * NN + rowbase + r],
                          __float_as_uint(m));
        }
        __syncthreads();   // cand consumed before next chunk overwrites it
    }

    // ---- epilogue: reduce colacc across the 8 warps ----
#pragma unroll
    for (int j = 0; j < KC; j++)
        u.colred[w * BC + lane * KC + j] = colacc[j];
    __syncthreads();
    if (tid < BC) {
        float m = u.colred[tid];
#pragma unroll
        for (int ww = 1; ww < NWARP; ww++)
            m = fminf(m, u.colred[ww * BC + tid]);
        atomicMin(&out[(size_t)(BB * NN) + (size_t)b * MM + colbase + tid],
                  __float_as_uint(m));
    }
}

extern "C" void kernel_launch(void* const* d_in, const int* in_sizes, int n_in,
                              void* d_out, int out_size)
{
    const float* xyz1 = (const float*)d_in[0];   // [B, N, 3]
    const float* xyz2 = (const float*)d_in[1];   // [B, M, 3]
    unsigned int* out = (unsigned int*)d_out;

    const int total = BB * NN + BB * MM;
    init_kernel<<<(total + TPB - 1) / TPB, TPB>>>(out);

    dim3 grid(NCB, ROWSPLIT, BB);   // (64, 16, 4) = 4096 blocks
    chamfer_fused<<<grid, TPB>>>(xyz1, xyz2, out);
}

// round 10
// speedup vs baseline: 1.0732x; 1.0019x over previous
#include <cuda_runtime.h>

// ChamferDistance_755914244601: B=4, N=M=8192, 3D points.
// Fused single pass; packed f32x2 FFMA2/FADD2 chain produces full distances
// (seed = s2 + s1 hoisted per row). Col mins in registers; row mins via STS
// cand + per-row reduce + uint atomicMin into d_out (distances >= 0).
// CH=256 chunks: full-block staging, 2 barriers per chunk.

#define BB 4
#define NN 8192
#define MM 8192
#define BC 256          // cols per block
#define KC 8            // cols per lane
#define NCP (KC / 2)    // colpairs per lane (4)
#define TPB 256
#define NWARP 8
#define CH 256          // rows per chunk (== TPB: one row per thread staging)
#define RPW (CH / NWARP)        // 32 rows per warp
#define ROWSPLIT 16
#define NROWS (NN / ROWSPLIT)   // 512
#define NCHUNK (NROWS / CH)     // 2
#define NCB (MM / BC)   // 32 col blocks

typedef unsigned long long ull;

static __device__ __forceinline__ ull pk2(float lo, float hi) {
    ull r; asm("mov.b64 %0, {%1, %2};" : "=l"(r) : "f"(lo), "f"(hi)); return r;
}
static __device__ __forceinline__ void upk2(ull v, float& lo, float& hi) {
    asm("mov.b64 {%0, %1}, %2;" : "=f"(lo), "=f"(hi) : "l"(v));
}
static __device__ __forceinline__ ull ffma2(ull a, ull b, ull c) {
    ull d; asm("fma.rn.f32x2 %0, %1, %2, %3;" : "=l"(d) : "l"(a), "l"(b), "l"(c)); return d;
}
static __device__ __forceinline__ ull fadd2(ull a, ull b) {
    ull d; asm("add.rn.f32x2 %0, %1, %2;" : "=l"(d) : "l"(a), "l"(b)); return d;
}

// Seed d_out (B*N + B*M floats) with FLT_MAX bit pattern.
__global__ void init_kernel(unsigned int* __restrict__ out)
{
    const int i = blockIdx.x * blockDim.x + threadIdx.x;
    if (i < BB * NN + BB * MM) out[i] = 0x7F7FFFFFu;   // FLT_MAX
}

__global__ void __launch_bounds__(TPB, 3)
chamfer_fused(const float* __restrict__ x1, const float* __restrict__ x2,
              unsigned int* __restrict__ out)
{
    __shared__ ulonglong2 RA[CH];      // (x,x),(y,y) per row   (4 KB)
    __shared__ ulonglong2 RB[CH];      // (z,z),(s1,s1) per row (4 KB)
    __shared__ float4 colsm[BC];       // (-2x,-2y,-2z,s2) per col (4 KB)
    __shared__ union {
        float cand[CH][33];            // row-min candidates (padded) (33 KB)
        float colred[NWARP * BC];      // epilogue col-reduce scratch
    } u;

    const int tid  = threadIdx.x;
    const int lane = tid & 31;
    const int w    = tid >> 5;
    const int b     = blockIdx.z;
    const int split = blockIdx.y;
    const int colbase  = blockIdx.x * BC;
    const int rowbase0 = split * NROWS;

    // ---- prologue: stage col tile and chunk-0 row tile ----
    {
        const float* p = x2 + ((size_t)b * MM + colbase + tid) * 3;
        float x = p[0], y = p[1], z = p[2];
        colsm[tid] = make_float4(-2.0f * x, -2.0f * y, -2.0f * z,
                                 x * x + y * y + z * z);
    }
    {
        const float* p = x1 + ((size_t)b * NN + rowbase0 + tid) * 3;
        float x = p[0], y = p[1], z = p[2];
        float s = x * x + y * y + z * z;
        RA[tid] = make_ulonglong2(pk2(x, x), pk2(y, y));
        RB[tid] = make_ulonglong2(pk2(z, z), pk2(s, s));
    }
    __syncthreads();

    // Lane's colpair cache (4 colpairs = 8 cols): 32 registers.
    ull cxx[NCP], cyy[NCP], czz[NCP], cww[NCP];
#pragma unroll
    for (int cp = 0; cp < NCP; cp++) {
        float4 a = colsm[lane * KC + 2 * cp];
        float4 c = colsm[lane * KC + 2 * cp + 1];
        cxx[cp] = pk2(a.x, c.x);
        cyy[cp] = pk2(a.y, c.y);
        czz[cp] = pk2(a.z, c.z);
        cww[cp] = pk2(a.w, c.w);
    }

    float colacc[KC];
#pragma unroll
    for (int j = 0; j < KC; j++) colacc[j] = 3.4e38f;

    // ---- main loop: 2 barriers per 256-row chunk ----
    for (int ch = 0; ch < NCHUNK; ch++) {
        const int rowbase = rowbase0 + ch * CH;

        // prefetch next chunk's row into registers (LDG latency overlaps compute)
        float prx = 0.f, pry = 0.f, prz = 0.f;
        if (ch + 1 < NCHUNK) {
            const float* p = x1 + ((size_t)b * NN + rowbase + CH + tid) * 3;
            prx = p[0]; pry = p[1]; prz = p[2];
        }

        // warp w handles rows [w*32, w*32+32) of this chunk
#pragma unroll 4
        for (int rr = 0; rr < RPW; rr++) {
            const int r = w * RPW + rr;
            const ulonglong2 ra = RA[r];   // LDS.128 broadcast
            const ulonglong2 rb = RB[r];
            // hoisted seeds: (s1 + s2) per colpair, off the critical path
            ull seed[NCP];
#pragma unroll
            for (int cp = 0; cp < NCP; cp++) seed[cp] = fadd2(cww[cp], rb.y);
            float racc0 = 3.4e38f, racc1 = 3.4e38f;
#pragma unroll
            for (int cp = 0; cp < NCP; cp++) {
                // c = (s1+s2) - 2*dot = full squared distance, both halves
                ull c = ffma2(cxx[cp], ra.x,
                        ffma2(cyy[cp], ra.y,
                        ffma2(czz[cp], rb.x, seed[cp])));
                float cl, chh; upk2(c, cl, chh);
                colacc[2 * cp]     = fminf(colacc[2 * cp], cl);
                colacc[2 * cp + 1] = fminf(colacc[2 * cp + 1], chh);
                racc0 = fminf(racc0, cl);
                racc1 = fminf(racc1, chh);
            }
            u.cand[r][lane] = fminf(racc0, racc1);
        }
        __syncthreads();   // cand complete; RA/RB reads done

        // per-row reduce: thread tid owns row tid (32 conflict-free LDS)
        {
            float m0 = u.cand[tid][0],  m1 = u.cand[tid][1];
            float m2 = u.cand[tid][2],  m3 = u.cand[tid][3];
#pragma unroll
            for (int i = 4; i < 32; i += 4) {
                m0 = fminf(m0, u.cand[tid][i]);
                m1 = fminf(m1, u.cand[tid][i + 1]);
                m2 = fminf(m2, u.cand[tid][i + 2]);
                m3 = fminf(m3, u.cand[tid][i + 3]);
            }
            float m = fminf(fminf(m0, m1), fminf(m2, m3));
            atomicMin(&out[(size_t)b * NN + rowbase + tid], __float_as_uint(m));
        }

        // stage next chunk's rows from the prefetched registers
        if (ch + 1 < NCHUNK) {
            float s = prx * prx + pry * pry + prz * prz;
            RA[tid] = make_ulonglong2(pk2(prx, prx), pk2(pry, pry));
            RB[tid] = make_ulonglong2(pk2(prz, prz), pk2(s, s));
        }
        __syncthreads();   // cand consumed + RA/RB restaged
    }

    // ---- epilogue: reduce colacc across the 8 warps ----
#pragma unroll
    for (int j = 0; j < KC; j++)
        u.colred[w * BC + lane * KC + j] = colacc[j];
    __syncthreads();
    {
        float m = u.colred[tid];
#pragma unroll
        for (int ww = 1; ww < NWARP; ww++)
            m = fminf(m, u.colred[ww * BC + tid]);
        atomicMin(&out[(size_t)(BB * NN) + (size_t)b * MM + colbase + tid],
                  __float_as_uint(m));
    }
}

extern "C" void kernel_launch(void* const* d_in, const int* in_sizes, int n_in,
                              void* d_out, int out_size)
{
    const float* xyz1 = (const float*)d_in[0];   // [B, N, 3]
    const float* xyz2 = (const float*)d_in[1];   // [B, M, 3]
    unsigned int* out = (unsigned int*)d_out;

    const int total = BB * NN + BB * MM;
    init_kernel<<<(total + TPB - 1) / TPB, TPB>>>(out);

    dim3 grid(NCB, ROWSPLIT, BB);   // (32, 16, 4) = 2048 blocks
    chamfer_fused<<<grid, TPB>>>(xyz1, xyz2, out);
}